// round 7
// baseline (speedup 1.0000x reference)
#include <cuda_runtime.h>
#include <cuda_fp16.h>
#include <cstdint>
#include <cstddef>

#define NPTS 65536
#define BB 4
#define CC 512
#define C3 1536
#define KK 256
#define HH 8
#define DH 64
#define NCH 256   // NPTS/KK

// ---------------- scratch (static device globals; no allocation) ----------------
__device__ float g_qkv[(size_t)NPTS * C3];     // gathered qkv, serialized order (fp32)
__device__ float g_clsqkv[BB * C3];            // cls token qkv
__device__ float g_clspart[NCH * CC];          // per-chunk cls attention row
__device__ __half g_Ah[(size_t)NPTS * CC];     // gathered feat hi (fp16)
__device__ __half g_Al[(size_t)NPTS * CC];     // gathered feat lo
__device__ __half g_att_h[(size_t)NPTS * CC];  // attention out hi (serialized)
__device__ __half g_att_l[(size_t)NPTS * CC];  // attention out lo
__device__ __half g_WqkvT[(size_t)C3 * CC];    // W^T fp16
__device__ __half g_WprojT[(size_t)CC * CC];

// =============== helpers ===============
__device__ __forceinline__ uint32_t smem_u32(const void* p) {
    uint32_t a;
    asm("{ .reg .u64 t; cvta.to.shared.u64 t, %1; cvt.u32.u64 %0, t; }" : "=r"(a) : "l"(p));
    return a;
}
__device__ __forceinline__ void ldsm_x4(uint32_t* r, uint32_t addr) {
    asm volatile("ldmatrix.sync.aligned.m8n8.x4.shared.b16 {%0,%1,%2,%3}, [%4];"
                 : "=r"(r[0]), "=r"(r[1]), "=r"(r[2]), "=r"(r[3]) : "r"(addr));
}
__device__ __forceinline__ void ldsm_x2(uint32_t* r, uint32_t addr) {
    asm volatile("ldmatrix.sync.aligned.m8n8.x2.shared.b16 {%0,%1}, [%2];"
                 : "=r"(r[0]), "=r"(r[1]) : "r"(addr));
}
__device__ __forceinline__ void ldsm_x2_t(uint32_t* r, uint32_t addr) {
    asm volatile("ldmatrix.sync.aligned.m8n8.x2.trans.shared.b16 {%0,%1}, [%2];"
                 : "=r"(r[0]), "=r"(r[1]) : "r"(addr));
}
__device__ __forceinline__ void mma_f16(float* c, const uint32_t* a, const uint32_t* b) {
    asm volatile(
        "mma.sync.aligned.m16n8k16.row.col.f32.f16.f16.f32 "
        "{%0,%1,%2,%3}, {%4,%5,%6,%7}, {%8,%9}, {%0,%1,%2,%3};"
        : "+f"(c[0]), "+f"(c[1]), "+f"(c[2]), "+f"(c[3])
        : "r"(a[0]), "r"(a[1]), "r"(a[2]), "r"(a[3]), "r"(b[0]), "r"(b[1]));
}
__device__ __forceinline__ uint32_t split_pack_h(float x, float y, uint32_t* lo) {
    __half2 hh = __floats2half2_rn(x, y);
    __half2 ll = __floats2half2_rn(x - __low2float(hh), y - __high2float(hh));
    *lo = *reinterpret_cast<uint32_t*>(&ll);
    return *reinterpret_cast<uint32_t*>(&hh);
}
__device__ __forceinline__ void cp_async16(uint32_t dst, const void* src) {
    asm volatile("cp.async.cg.shared.global [%0], [%1], 16;" :: "r"(dst), "l"(src) : "memory");
}
#define CP_COMMIT() asm volatile("cp.async.commit_group;" ::: "memory")
#define CP_WAIT1()  asm volatile("cp.async.wait_group 1;" ::: "memory")

// ---------------- W transpose to fp16 ----------------
__global__ __launch_bounds__(256)
void conv_wt_kernel(const float* __restrict__ W, __half* __restrict__ T, int K, int N)
{
    __shared__ float t[32][33];
    int n0 = blockIdx.x * 32, k0 = blockIdx.y * 32;
    int tx = threadIdx.x & 31, ty = threadIdx.x >> 5;
    #pragma unroll
    for (int j = 0; j < 32; j += 8)
        t[ty + j][tx] = W[(size_t)(k0 + ty + j) * N + n0 + tx];
    __syncthreads();
    #pragma unroll
    for (int j = 0; j < 32; j += 8) {
        int n = n0 + ty + j, k = k0 + tx;
        T[(size_t)n * K + k] = __float2half_rn(t[tx][ty + j]);
    }
}

// ---------------- feat gather + fp16 split ----------------
__global__ __launch_bounds__(256)
void conv_feat_kernel(const float* __restrict__ feat, const int* __restrict__ order)
{
    size_t idx = (size_t)blockIdx.x * 256 + threadIdx.x;
    int m = (int)(idx >> 7);
    int u = (int)(idx & 127);
    const float4 v = *(const float4*)(feat + (size_t)order[m] * CC + u * 4);
    uint32_t l01, l23;
    uint32_t h01 = split_pack_h(v.x, v.y, &l01);
    uint32_t h23 = split_pack_h(v.z, v.w, &l23);
    *(uint2*)(g_Ah + (size_t)m * CC + u * 4) = make_uint2(h01, h23);
    *(uint2*)(g_Al + (size_t)m * CC + u * 4) = make_uint2(l01, l23);
}

// ---------------- cp.async GEMM: 128x256 tile, warp 64x64, Kc=32, fp16 2-term ----------------
#define PROWB  80
#define PTILE  (128 * PROWB)       // 10240  (A tile: 128 rows)
#define BTILE  (256 * PROWB)       // 20480  (B tile: 256 rows)
#define PSTAGE (2 * PTILE + BTILE) // 40960
#define SMHDR  1536
#define GSMEM  (SMHDR + 3 * PSTAGE)   // 124416

template<bool SCATTER>
__global__ __launch_bounds__(256, 1)
void gemm_async_kernel(const __half* __restrict__ Ah, const __half* __restrict__ Al,
                       const __half* __restrict__ Bh,
                       const float* __restrict__ bias, float* __restrict__ C,
                       const int* __restrict__ order, int Ntot)
{
    extern __shared__ char sm[];
    const uint32_t sb = smem_u32(sm);
    const int tid = threadIdx.x, wid = tid >> 5, lane = tid & 31;
    const int n0 = blockIdx.x * 256, m0 = blockIdx.y * 128;
    float* bias_s = (float*)sm;            // 256 floats
    int*   rowidx = (int*)(sm + 1024);     // 128 ints

    const int cr = tid >> 2;        // 0..63
    const int cu = (tid & 3) * 16;  // byte offset within 64B k-chunk row

    auto issue_stage = [&](int c, int stage) {
        const int k0 = c * 32;
        const uint32_t dbase = sb + SMHDR + stage * PSTAGE;
        #pragma unroll
        for (int i = 0; i < 4; i++) {   // A hi/lo: rows cr, cr+64
            const int tile = i >> 1;
            const int r = (i & 1) * 64 + cr;
            const __half* src = (tile ? Al : Ah) + (size_t)(m0 + r) * CC + k0;
            cp_async16(dbase + tile * PTILE + r * PROWB + cu, (const char*)src + cu);
        }
        #pragma unroll
        for (int i = 0; i < 4; i++) {   // B: rows cr, cr+64, cr+128, cr+192
            const int r = i * 64 + cr;
            const __half* src = Bh + (size_t)(n0 + r) * CC + k0;
            cp_async16(dbase + 2 * PTILE + r * PROWB + cu, (const char*)src + cu);
        }
    };

    issue_stage(0, 0); CP_COMMIT();
    issue_stage(1, 1); CP_COMMIT();

    bias_s[tid] = bias[n0 + tid];
    if (tid < 128 && SCATTER) rowidx[tid] = order[m0 + tid];
    __syncthreads();

    const int wm = (wid & 1) * 64;
    const int wn = (wid >> 1) * 64;

    float acc[4][8][4];
    #pragma unroll
    for (int nt = 0; nt < 8; nt++) {
        float b0 = bias_s[wn + nt * 8 + 2 * (lane & 3)];
        float b1 = bias_s[wn + nt * 8 + 2 * (lane & 3) + 1];
        #pragma unroll
        for (int mt = 0; mt < 4; mt++) {
            acc[mt][nt][0] = b0; acc[mt][nt][1] = b1;
            acc[mt][nt][2] = b0; acc[mt][nt][3] = b1;
        }
    }

    const uint32_t a_lm = sb + SMHDR + (wm + (lane & 15)) * PROWB + ((lane >> 4) & 1) * 16;
    const uint32_t b_lm = sb + SMHDR + 2 * PTILE + (wn + (lane & 7)) * PROWB
                          + ((lane >> 3) & 1) * 16;

    const int NC = CC / 32;   // 16
    #pragma unroll 1
    for (int c = 0; c < NC; c++) {
        CP_WAIT1();
        __syncthreads();
        if (c + 2 < NC) issue_stage(c + 2, (c + 2) % 3);
        CP_COMMIT();

        const uint32_t abase = a_lm + (c % 3) * PSTAGE;
        const uint32_t bbase = b_lm + (c % 3) * PSTAGE;
        #pragma unroll
        for (int ks = 0; ks < 2; ks++) {
            const int ko = ks * 32;
            uint32_t ah[4][4], al[4][4], bh[8][2];
            #pragma unroll
            for (int mt = 0; mt < 4; mt++) {
                ldsm_x4(ah[mt], abase + mt * 16 * PROWB + ko);
                ldsm_x4(al[mt], abase + PTILE + mt * 16 * PROWB + ko);
            }
            #pragma unroll
            for (int nt = 0; nt < 8; nt++)
                ldsm_x2(bh[nt], bbase + nt * 8 * PROWB + ko);
            #pragma unroll
            for (int mt = 0; mt < 4; mt++)
                #pragma unroll
                for (int nt = 0; nt < 8; nt++) {
                    mma_f16(acc[mt][nt], ah[mt], bh[nt]);
                    mma_f16(acc[mt][nt], al[mt], bh[nt]);
                }
        }
    }

    #pragma unroll
    for (int mt = 0; mt < 4; mt++) {
        int lrow = wm + mt * 16 + (lane >> 2);
        int d0 = SCATTER ? rowidx[lrow]     : (m0 + lrow);
        int d1 = SCATTER ? rowidx[lrow + 8] : (m0 + lrow + 8);
        #pragma unroll
        for (int nt = 0; nt < 8; nt++) {
            int col = n0 + wn + nt * 8 + 2 * (lane & 3);
            *(float2*)(C + (size_t)d0 * Ntot + col) =
                make_float2(acc[mt][nt][0], acc[mt][nt][1]);
            *(float2*)(C + (size_t)d1 * Ntot + col) =
                make_float2(acc[mt][nt][2], acc[mt][nt][3]);
        }
    }
}

// ---------------- cls qkv: parallel k-split, grid 48 ----------------
__global__ __launch_bounds__(256)
void cls_qkv_kernel(const float* __restrict__ cls_tokens,
                    const float* __restrict__ Wqkv,
                    const float* __restrict__ bqkv)
{
    __shared__ float ct[BB * CC];
    __shared__ float red[8][BB][32];
    const int tid = threadIdx.x, lane = tid & 31, seg = tid >> 5;
    for (int i = tid; i < BB * CC; i += 256) ct[i] = cls_tokens[i];
    __syncthreads();
    const int n = blockIdx.x * 32 + lane;
    float acc[BB] = {0.f, 0.f, 0.f, 0.f};
    for (int k = seg * 64; k < seg * 64 + 64; k++) {
        float w = Wqkv[(size_t)k * C3 + n];
        #pragma unroll
        for (int b = 0; b < BB; b++) acc[b] += ct[b * CC + k] * w;
    }
    #pragma unroll
    for (int b = 0; b < BB; b++) red[seg][b][lane] = acc[b];
    __syncthreads();
    if (seg < BB) {
        float s = bqkv[n];
        #pragma unroll
        for (int j = 0; j < 8; j++) s += red[j][seg][lane];
        g_clsqkv[seg * C3 + n] = s;
    }
}

// ---------------- tensor-core attention (token queries), fp16 2-term ----------------
#define NP 272
#define KROWB 144
#define ATT_SMEM (2 * NP * KROWB)   // 78336

__global__ __launch_bounds__(256)
void attn_mma_kernel(const int* __restrict__ offset)
{
    extern __shared__ char sm[];
    char* KhB = sm;
    char* VhB = sm + NP * KROWB;
    const uint32_t sb = smem_u32(sm);
    const uint32_t KhU = sb;
    const uint32_t VhU = sb + NP * KROWB;

    const int ci = blockIdx.x, h = blockIdx.y, tid = threadIdx.x;
    const int wid = tid >> 5, lane = tid & 31;
    const int cs = ci * KK;
    int b = 0;
    #pragma unroll
    for (int j = 0; j < BB; j++) b += (offset[j] <= cs) ? 1 : 0;
    const float* qkvbase = g_qkv + (size_t)cs * C3;
    const float* clsrow  = g_clsqkv + b * C3;
    const int koff = CC + h * DH, voff = 2 * CC + h * DH;

    for (int idx = tid; idx < 2 * NP * 16; idx += 256) {
        int kv = idx >= NP * 16;
        int i  = kv ? idx - NP * 16 : idx;
        int t = i >> 4, d4 = (i & 15) << 2;
        int off = kv ? voff : koff;
        float4 v = make_float4(0.f, 0.f, 0.f, 0.f);
        if (t == 0)       v = *(const float4*)(clsrow + off + d4);
        else if (t <= KK) v = *(const float4*)(qkvbase + (size_t)(t - 1) * C3 + off + d4);
        __half2 h01 = __floats2half2_rn(v.x, v.y);
        __half2 h23 = __floats2half2_rn(v.z, v.w);
        char* hB = (kv ? VhB : KhB) + t * KROWB + d4 * 2;
        *(uint2*)hB = make_uint2(*(uint32_t*)&h01, *(uint32_t*)&h23);
    }
    __syncthreads();

    const int r0 = lane >> 2;
    const int qp = (lane & 3) * 2;

    #pragma unroll 1
    for (int mt = wid; mt < 16; mt += 8) {
        const float* p0 = qkvbase + (size_t)(mt * 16 + r0) * C3 + h * DH;
        const float* p1 = p0 + 8 * C3;

        float acc[34][4];
        #pragma unroll
        for (int nt = 0; nt < 34; nt++)
            acc[nt][0] = acc[nt][1] = acc[nt][2] = acc[nt][3] = 0.f;

        #pragma unroll
        for (int kt = 0; kt < 4; kt++) {
            float2 q00 = *(const float2*)(p0 + kt * 16 + qp);
            float2 q10 = *(const float2*)(p1 + kt * 16 + qp);
            float2 q01 = *(const float2*)(p0 + kt * 16 + qp + 8);
            float2 q11 = *(const float2*)(p1 + kt * 16 + qp + 8);
            uint32_t qh[4], ql[4];
            qh[0] = split_pack_h(q00.x * 0.125f, q00.y * 0.125f, &ql[0]);
            qh[1] = split_pack_h(q10.x * 0.125f, q10.y * 0.125f, &ql[1]);
            qh[2] = split_pack_h(q01.x * 0.125f, q01.y * 0.125f, &ql[2]);
            qh[3] = split_pack_h(q11.x * 0.125f, q11.y * 0.125f, &ql[3]);
            const uint32_t kaddr = KhU + (lane & 7) * KROWB + ((lane >> 3) & 1) * 16 + kt * 32;
            #pragma unroll
            for (int nt = 0; nt < 34; nt++) {
                uint32_t bh[2];
                ldsm_x2(bh, kaddr + nt * 8 * KROWB);
                mma_f16(acc[nt], qh, bh);
                mma_f16(acc[nt], ql, bh);
            }
        }

        if (qp != 0) { acc[32][0] = -1e30f; acc[32][2] = -1e30f; }
        acc[32][1] = -1e30f; acc[32][3] = -1e30f;
        acc[33][0] = acc[33][1] = acc[33][2] = acc[33][3] = -1e30f;

        float m0 = -1e30f, m1 = -1e30f;
        #pragma unroll
        for (int nt = 0; nt < 34; nt++) {
            m0 = fmaxf(m0, fmaxf(acc[nt][0], acc[nt][1]));
            m1 = fmaxf(m1, fmaxf(acc[nt][2], acc[nt][3]));
        }
        m0 = fmaxf(m0, __shfl_xor_sync(0xffffffffu, m0, 1));
        m0 = fmaxf(m0, __shfl_xor_sync(0xffffffffu, m0, 2));
        m1 = fmaxf(m1, __shfl_xor_sync(0xffffffffu, m1, 1));
        m1 = fmaxf(m1, __shfl_xor_sync(0xffffffffu, m1, 2));
        float s0 = 0.f, s1 = 0.f;
        #pragma unroll
        for (int nt = 0; nt < 34; nt++) {
            acc[nt][0] = __expf(acc[nt][0] - m0);
            acc[nt][1] = __expf(acc[nt][1] - m0);
            acc[nt][2] = __expf(acc[nt][2] - m1);
            acc[nt][3] = __expf(acc[nt][3] - m1);
            s0 += acc[nt][0] + acc[nt][1];
            s1 += acc[nt][2] + acc[nt][3];
        }
        s0 += __shfl_xor_sync(0xffffffffu, s0, 1);
        s0 += __shfl_xor_sync(0xffffffffu, s0, 2);
        s1 += __shfl_xor_sync(0xffffffffu, s1, 1);
        s1 += __shfl_xor_sync(0xffffffffu, s1, 2);
        const float inv0 = 1.f / s0, inv1 = 1.f / s1;

        float o[8][4];
        #pragma unroll
        for (int nt = 0; nt < 8; nt++)
            o[nt][0] = o[nt][1] = o[nt][2] = o[nt][3] = 0.f;

        #pragma unroll
        for (int kt = 0; kt < 17; kt++) {
            uint32_t ah[4], al[4];
            ah[0] = split_pack_h(acc[2*kt][0] * inv0,   acc[2*kt][1] * inv0,   &al[0]);
            ah[1] = split_pack_h(acc[2*kt][2] * inv1,   acc[2*kt][3] * inv1,   &al[1]);
            ah[2] = split_pack_h(acc[2*kt+1][0] * inv0, acc[2*kt+1][1] * inv0, &al[2]);
            ah[3] = split_pack_h(acc[2*kt+1][2] * inv1, acc[2*kt+1][3] * inv1, &al[3]);
            const uint32_t vaddr = VhU + (kt * 16 + (lane & 15)) * KROWB;
            #pragma unroll
            for (int nt = 0; nt < 8; nt++) {
                uint32_t bh[2];
                ldsm_x2_t(bh, vaddr + nt * 16);
                mma_f16(o[nt], ah, bh);
                mma_f16(o[nt], al, bh);
            }
        }

        const size_t row0 = (size_t)(cs + mt * 16 + r0) * CC + h * DH;
        const size_t row1 = row0 + 8 * CC;
        #pragma unroll
        for (int nt = 0; nt < 8; nt++) {
            uint32_t lo;
            uint32_t hi = split_pack_h(o[nt][0], o[nt][1], &lo);
            *(uint32_t*)(g_att_h + row0 + nt * 8 + qp) = hi;
            *(uint32_t*)(g_att_l + row0 + nt * 8 + qp) = lo;
            hi = split_pack_h(o[nt][2], o[nt][3], &lo);
            *(uint32_t*)(g_att_h + row1 + nt * 8 + qp) = hi;
            *(uint32_t*)(g_att_l + row1 + nt * 8 + qp) = lo;
        }
    }
}

// ---------------- cls-query attention ----------------
__global__ __launch_bounds__(256)
void cls_attn_kernel(const int* __restrict__ offset)
{
    __shared__ float sS[HH][257];
    const int ci = blockIdx.x, tid = threadIdx.x;
    const int h = tid >> 5, lane = tid & 31;
    const int cs = ci * KK;
    int b = 0;
    #pragma unroll
    for (int j = 0; j < BB; j++) b += (offset[j] <= cs) ? 1 : 0;
    const float* qkvbase = g_qkv + (size_t)cs * C3;
    const float* clsrow  = g_clsqkv + b * C3;
    const int koff = CC + h * DH, voff = 2 * CC + h * DH;

    const float q0 = clsrow[h * DH + lane] * 0.125f;
    const float q1 = clsrow[h * DH + lane + 32] * 0.125f;

    for (int j = 0; j < 257; j++) {
        const float* kr = (j == 0) ? (clsrow + koff)
                                   : (qkvbase + (size_t)(j - 1) * C3 + koff);
        float part = q0 * kr[lane] + q1 * kr[lane + 32];
        #pragma unroll
        for (int o = 16; o; o >>= 1) part += __shfl_xor_sync(0xffffffffu, part, o);
        if (lane == 0) sS[h][j] = part;
    }
    __syncwarp();

    float m = -1e30f;
    for (int j = lane; j < 257; j += 32) m = fmaxf(m, sS[h][j]);
    #pragma unroll
    for (int o = 16; o; o >>= 1) m = fmaxf(m, __shfl_xor_sync(0xffffffffu, m, o));
    float s = 0.f;
    for (int j = lane; j < 257; j += 32) {
        float e = __expf(sS[h][j] - m);
        sS[h][j] = e;
        s += e;
    }
    #pragma unroll
    for (int o = 16; o; o >>= 1) s += __shfl_xor_sync(0xffffffffu, s, o);
    const float inv = 1.f / s;
    __syncwarp();

    float o0 = 0.f, o1 = 0.f;
    for (int j = 0; j < 257; j++) {
        const float* vr = (j == 0) ? (clsrow + voff)
                                   : (qkvbase + (size_t)(j - 1) * C3 + voff);
        float p = sS[h][j] * inv;
        o0 += p * vr[lane];
        o1 += p * vr[lane + 32];
    }
    g_clspart[ci * CC + h * DH + lane]      = o0;
    g_clspart[ci * CC + h * DH + lane + 32] = o1;
}

// ---------------- cls reduce ----------------
__global__ __launch_bounds__(256)
void cls_reduce_kernel(const int* __restrict__ offset, float* __restrict__ out_cls)
{
    int gid = blockIdx.x * 256 + threadIdx.x;
    int b = gid >> 9;
    int c = gid & (CC - 1);
    int start = (b == 0) ? 0 : offset[b - 1];
    int end = offset[b];
    int ch0 = start / KK, ch1 = end / KK;
    float s = 0.f;
    for (int ch = ch0; ch < ch1; ch++) s += g_clspart[ch * CC + c];
    out_cls[gid] = s / (float)(ch1 - ch0);
}

// ---------------- launch ----------------
extern "C" void kernel_launch(void* const* d_in, const int* in_sizes, int n_in,
                              void* d_out, int out_size)
{
    const float* feat       = (const float*)d_in[0];
    const float* cls_tokens = (const float*)d_in[1];
    const float* Wqkv       = (const float*)d_in[2];
    const float* bqkv       = (const float*)d_in[3];
    const float* Wproj      = (const float*)d_in[4];
    const float* bproj      = (const float*)d_in[5];
    const int*   order      = (const int*)d_in[6];
    const int*   offset     = (const int*)d_in[8];

    float* out_feat = (float*)d_out;
    float* out_cls  = out_feat + (size_t)NPTS * CC;

    void *qkvp = nullptr;
    void *ah = nullptr, *al = nullptr, *ath = nullptr, *atl = nullptr;
    void *wq = nullptr, *wp = nullptr;
    cudaGetSymbolAddress(&qkvp, g_qkv);
    cudaGetSymbolAddress(&ah, g_Ah);
    cudaGetSymbolAddress(&al, g_Al);
    cudaGetSymbolAddress(&ath, g_att_h);
    cudaGetSymbolAddress(&atl, g_att_l);
    cudaGetSymbolAddress(&wq, g_WqkvT);
    cudaGetSymbolAddress(&wp, g_WprojT);

    cudaFuncSetAttribute(attn_mma_kernel, cudaFuncAttributeMaxDynamicSharedMemorySize,
                         ATT_SMEM);
    cudaFuncSetAttribute(gemm_async_kernel<false>,
                         cudaFuncAttributeMaxDynamicSharedMemorySize, GSMEM);
    cudaFuncSetAttribute(gemm_async_kernel<true>,
                         cudaFuncAttributeMaxDynamicSharedMemorySize, GSMEM);

    // 0. weight transpose (fp16), feat gather+split (fp16)
    conv_wt_kernel<<<dim3(C3 / 32, CC / 32), 256>>>(Wqkv, (__half*)wq, CC, C3);
    conv_wt_kernel<<<dim3(CC / 32, CC / 32), 256>>>(Wproj, (__half*)wp, CC, CC);
    conv_feat_kernel<<<(NPTS * (CC / 4)) / 256, 256>>>(feat, order);
    // 1. cls token qkv
    cls_qkv_kernel<<<C3 / 32, 256>>>(cls_tokens, Wqkv, bqkv);
    // 2. qkv GEMM (128x256 tiles)
    gemm_async_kernel<false><<<dim3(C3 / 256, NPTS / 128), 256, GSMEM>>>(
        (const __half*)ah, (const __half*)al, (const __half*)wq,
        bqkv, (float*)qkvp, order, C3);
    // 3. attention
    attn_mma_kernel<<<dim3(NCH, HH), 256, ATT_SMEM>>>(offset);
    cls_attn_kernel<<<NCH, 256>>>(offset);
    // 4. proj GEMM with scatter (128x256 tiles)
    gemm_async_kernel<true><<<dim3(CC / 256, NPTS / 128), 256, GSMEM>>>(
        (const __half*)ath, (const __half*)atl, (const __half*)wp,
        bproj, out_feat, order, CC);
    // 5. cls reduction
    cls_reduce_kernel<<<(BB * CC) / 256, 256>>>(offset, out_cls);
}